// round 1
// baseline (speedup 1.0000x reference)
#include <cuda_runtime.h>
#include <cuda_bf16.h>
#include <math.h>

// Problem constants (fixed shapes)
#define T_TOK 8192
#define D_DIM 512
#define H_DIM 1024
#define E_NUM 8
#define K_TOP 2
#define PAIRS (T_TOK * K_TOP)   // 16384

// ---------------- device scratch (no allocations allowed) ----------------
__device__ float g_Hbuf[(size_t)PAIRS * H_DIM];   // 67 MB intermediate activations
__device__ int   g_e0[T_TOK], g_e1[T_TOK];
__device__ float g_g0[T_TOK], g_g1[T_TOK];
__device__ int   g_cnt[E_NUM], g_off[E_NUM], g_cursor[E_NUM];
__device__ int   g_tok[PAIRS];
__device__ float g_gate[PAIRS];

// ---------------- 1) gating: logits, top-2, softmax ----------------
// block = 128 threads (1 token each), grid = 64
__global__ void gate_kernel(const float* __restrict__ x,
                            const float* __restrict__ Wg) {
    __shared__ float xs[128][68];   // 68 stride: float4-aligned rows
    __shared__ float wgs[64][8];
    const int tid = threadIdx.x;
    const int t0  = blockIdx.x * 128;
    float acc[E_NUM];
#pragma unroll
    for (int e = 0; e < E_NUM; e++) acc[e] = 0.f;

    for (int k0 = 0; k0 < D_DIM; k0 += 64) {
        // Wg chunk: 64x8 = 512 floats
#pragma unroll
        for (int i = 0; i < 4; i++) {
            int idx = tid + i * 128;
            wgs[idx >> 3][idx & 7] = Wg[(k0 + (idx >> 3)) * E_NUM + (idx & 7)];
        }
        // x tile: 128 rows x 64 cols, coalesced float4
#pragma unroll
        for (int i = 0; i < 16; i++) {
            int f4  = i * 128 + tid;         // 2048 float4
            int row = f4 >> 4;               // 16 float4 per row
            int c4  = f4 & 15;
            float4 v = *(const float4*)(x + (size_t)(t0 + row) * D_DIM + k0 + c4 * 4);
            *(float4*)&xs[row][c4 * 4] = v;
        }
        __syncthreads();
#pragma unroll 8
        for (int k = 0; k < 64; k++) {
            float xv = xs[tid][k];
#pragma unroll
            for (int e = 0; e < E_NUM; e++) acc[e] = fmaf(xv, wgs[k][e], acc[e]);
        }
        __syncthreads();
    }

    // top-2 with first-occurrence tie break (matches lax.top_k)
    int e0 = 0; float v0 = acc[0];
#pragma unroll
    for (int e = 1; e < E_NUM; e++) if (acc[e] > v0) { v0 = acc[e]; e0 = e; }
    int e1 = -1; float v1 = -INFINITY;
#pragma unroll
    for (int e = 0; e < E_NUM; e++) if (e != e0 && acc[e] > v1) { v1 = acc[e]; e1 = e; }
    float p1 = __expf(v1 - v0);
    float inv = 1.f / (1.f + p1);
    int t = t0 + tid;
    g_e0[t] = e0; g_e1[t] = e1;
    g_g0[t] = inv; g_g1[t] = p1 * inv;
}

// ---------------- 2) setup: counts/importance reduction, offsets, losses ----
// single block of 256 threads; deterministic tree reduction
__global__ void setup_kernel(float* __restrict__ out) {
    __shared__ float simp[E_NUM][256];
    __shared__ int   scnt[E_NUM][256];
    const int tid = threadIdx.x;
    float imp[E_NUM]; int cnt[E_NUM];
#pragma unroll
    for (int e = 0; e < E_NUM; e++) { imp[e] = 0.f; cnt[e] = 0; }
    for (int t = tid; t < T_TOK; t += 256) {
        int a = g_e0[t]; imp[a] += g_g0[t]; cnt[a]++;
        int b = g_e1[t]; imp[b] += g_g1[t]; cnt[b]++;
    }
#pragma unroll
    for (int e = 0; e < E_NUM; e++) { simp[e][tid] = imp[e]; scnt[e][tid] = cnt[e]; }
    __syncthreads();
    for (int s = 128; s > 0; s >>= 1) {
        if (tid < s) {
#pragma unroll
            for (int e = 0; e < E_NUM; e++) {
                simp[e][tid] += simp[e][tid + s];
                scnt[e][tid] += scnt[e][tid + s];
            }
        }
        __syncthreads();
    }
    if (tid == 0) {
        const float eps = 1e-10f;
        int off = 0;
        float mi = 0.f, ml = 0.f;
#pragma unroll
        for (int e = 0; e < E_NUM; e++) {
            g_off[e] = off; g_cnt[e] = scnt[e][0]; g_cursor[e] = 0;
            off += scnt[e][0];
            mi += simp[e][0];
            ml += (float)scnt[e][0];
        }
        mi /= E_NUM; ml /= E_NUM;
        float vi = 0.f, vl = 0.f;
#pragma unroll
        for (int e = 0; e < E_NUM; e++) {
            float di = simp[e][0] - mi; vi += di * di;
            float dl = (float)scnt[e][0] - ml; vl += dl * dl;
        }
        vi /= (E_NUM - 1); vl /= (E_NUM - 1);
        out[(size_t)T_TOK * D_DIM]     = vi / (mi * mi + eps);
        out[(size_t)T_TOK * D_DIM + 1] = vl / (ml * ml + eps);
    }
}

// ---------------- 3) scatter tokens into per-expert lists ----------------
__global__ void scatter_kernel() {
    int t = blockIdx.x * 256 + threadIdx.x;
    if (t >= T_TOK) return;
    {
        int e = g_e0[t];
        int p = atomicAdd(&g_cursor[e], 1);
        int s = g_off[e] + p;
        g_tok[s] = t; g_gate[s] = g_g0[t];
    }
    {
        int e = g_e1[t];
        int p = atomicAdd(&g_cursor[e], 1);
        int s = g_off[e] + p;
        g_tok[s] = t; g_gate[s] = g_g1[t];
    }
}

// ---------------- GEMM tiling constants ----------------
#define BM 128
#define BN 128
#define BK 16
#define TM 8
#define TN 8
// 256 threads = 16x16 thread grid

// ---------------- 4) GEMM1: H = relu(gather(x) @ W1_e + b1_e) ----------------
// grid (64, H_DIM/BN, E), early exit on empty tiles
__global__ __launch_bounds__(256, 2)
void gemm1_kernel(const float* __restrict__ x,
                  const float* __restrict__ W1,
                  const float* __restrict__ b1) {
    const int e   = blockIdx.z;
    const int cnt = g_cnt[e];
    const int m0  = blockIdx.x * BM;
    if (m0 >= cnt) return;
    const int n0   = blockIdx.y * BN;
    const int off  = g_off[e];
    const int mrem = cnt - m0;
    const float* B = W1 + (size_t)e * D_DIM * H_DIM;

    __shared__ float As[BK][BM + 4];
    __shared__ float Bs[BK][BN];
    __shared__ int   toks[BM];

    const int tid = threadIdx.x;
    const int tx = tid & 15, ty = tid >> 4;

    if (tid < BM) toks[tid] = (tid < mrem) ? g_tok[off + m0 + tid] : -1;
    __syncthreads();

    float acc[TM][TN];
#pragma unroll
    for (int i = 0; i < TM; i++)
#pragma unroll
        for (int j = 0; j < TN; j++) acc[i][j] = 0.f;

    for (int k0 = 0; k0 < D_DIM; k0 += BK) {
        // A tile: 128 rows x 16 k (512 float4), gathered; store transposed
#pragma unroll
        for (int i = 0; i < 2; i++) {
            int f4  = tid + i * 256;
            int row = f4 >> 2, kq = f4 & 3;
            float4 v = make_float4(0.f, 0.f, 0.f, 0.f);
            int tok = toks[row];
            if (tok >= 0) v = *(const float4*)(x + (size_t)tok * D_DIM + k0 + kq * 4);
            As[kq * 4 + 0][row] = v.x;
            As[kq * 4 + 1][row] = v.y;
            As[kq * 4 + 2][row] = v.z;
            As[kq * 4 + 3][row] = v.w;
        }
        // B tile: 16 rows x 128 cols
#pragma unroll
        for (int i = 0; i < 2; i++) {
            int f4  = tid + i * 256;
            int row = f4 >> 5, c4 = f4 & 31;
            *(float4*)&Bs[row][c4 * 4] =
                *(const float4*)(B + (size_t)(k0 + row) * H_DIM + n0 + c4 * 4);
        }
        __syncthreads();
#pragma unroll
        for (int kk = 0; kk < BK; kk++) {
            float4 a0 = *(const float4*)&As[kk][ty * TM];
            float4 a1 = *(const float4*)&As[kk][ty * TM + 4];
            float4 b0 = *(const float4*)&Bs[kk][tx * TN];
            float4 b1v = *(const float4*)&Bs[kk][tx * TN + 4];
            float a[TM] = {a0.x, a0.y, a0.z, a0.w, a1.x, a1.y, a1.z, a1.w};
            float b[TN] = {b0.x, b0.y, b0.z, b0.w, b1v.x, b1v.y, b1v.z, b1v.w};
#pragma unroll
            for (int i = 0; i < TM; i++)
#pragma unroll
                for (int j = 0; j < TN; j++) acc[i][j] = fmaf(a[i], b[j], acc[i][j]);
        }
        __syncthreads();
    }

    const float* bias = b1 + (size_t)e * H_DIM + n0;
#pragma unroll
    for (int i = 0; i < TM; i++) {
        int row = ty * TM + i;
        if (row < mrem) {
            float* dst = g_Hbuf + (size_t)(off + m0 + row) * H_DIM + n0;
#pragma unroll
            for (int j = 0; j < TN; j++) {
                int n = tx * TN + j;
                dst[n] = fmaxf(acc[i][j] + bias[n], 0.f);
            }
        }
    }
}

// ---------------- 5) GEMM2: out += gate * (H @ W2_e + b2_e) ----------------
// grid (64, D_DIM/BN, E)
__global__ __launch_bounds__(256, 2)
void gemm2_kernel(const float* __restrict__ W2,
                  const float* __restrict__ b2,
                  float* __restrict__ out) {
    const int e   = blockIdx.z;
    const int cnt = g_cnt[e];
    const int m0  = blockIdx.x * BM;
    if (m0 >= cnt) return;
    const int n0   = blockIdx.y * BN;
    const int off  = g_off[e];
    const int mrem = cnt - m0;
    const float* A = g_Hbuf + (size_t)(off + m0) * H_DIM;
    const float* B = W2 + (size_t)e * H_DIM * D_DIM;

    __shared__ float As[BK][BM + 4];
    __shared__ float Bs[BK][BN];
    __shared__ int   stok[BM];
    __shared__ float sgate[BM];

    const int tid = threadIdx.x;
    const int tx = tid & 15, ty = tid >> 4;

    if (tid < BM) {
        if (tid < mrem) {
            int s = off + m0 + tid;
            stok[tid]  = g_tok[s];
            sgate[tid] = g_gate[s];
        } else {
            stok[tid] = -1; sgate[tid] = 0.f;
        }
    }
    __syncthreads();

    float acc[TM][TN];
#pragma unroll
    for (int i = 0; i < TM; i++)
#pragma unroll
        for (int j = 0; j < TN; j++) acc[i][j] = 0.f;

    for (int k0 = 0; k0 < H_DIM; k0 += BK) {
#pragma unroll
        for (int i = 0; i < 2; i++) {
            int f4  = tid + i * 256;
            int row = f4 >> 2, kq = f4 & 3;
            float4 v = make_float4(0.f, 0.f, 0.f, 0.f);
            if (row < mrem) v = *(const float4*)(A + (size_t)row * H_DIM + k0 + kq * 4);
            As[kq * 4 + 0][row] = v.x;
            As[kq * 4 + 1][row] = v.y;
            As[kq * 4 + 2][row] = v.z;
            As[kq * 4 + 3][row] = v.w;
        }
#pragma unroll
        for (int i = 0; i < 2; i++) {
            int f4  = tid + i * 256;
            int row = f4 >> 5, c4 = f4 & 31;
            *(float4*)&Bs[row][c4 * 4] =
                *(const float4*)(B + (size_t)(k0 + row) * D_DIM + n0 + c4 * 4);
        }
        __syncthreads();
#pragma unroll
        for (int kk = 0; kk < BK; kk++) {
            float4 a0 = *(const float4*)&As[kk][ty * TM];
            float4 a1 = *(const float4*)&As[kk][ty * TM + 4];
            float4 b0 = *(const float4*)&Bs[kk][tx * TN];
            float4 b1v = *(const float4*)&Bs[kk][tx * TN + 4];
            float a[TM] = {a0.x, a0.y, a0.z, a0.w, a1.x, a1.y, a1.z, a1.w};
            float b[TN] = {b0.x, b0.y, b0.z, b0.w, b1v.x, b1v.y, b1v.z, b1v.w};
#pragma unroll
            for (int i = 0; i < TM; i++)
#pragma unroll
                for (int j = 0; j < TN; j++) acc[i][j] = fmaf(a[i], b[j], acc[i][j]);
        }
        __syncthreads();
    }

    const float* bias = b2 + (size_t)e * D_DIM + n0;
#pragma unroll
    for (int i = 0; i < TM; i++) {
        int row = ty * TM + i;
        if (row < mrem) {
            int tok = stok[row];
            float g = sgate[row];
            float* dst = out + (size_t)tok * D_DIM + n0;
#pragma unroll
            for (int j = 0; j < TN; j++) {
                int n = tx * TN + j;
                atomicAdd(&dst[n], g * (acc[i][j] + bias[n]));
            }
        }
    }
}

// ---------------- launch ----------------
extern "C" void kernel_launch(void* const* d_in, const int* in_sizes, int n_in,
                              void* d_out, int out_size) {
    const float* x  = (const float*)d_in[0];
    const float* Wg = (const float*)d_in[1];
    const float* W1 = (const float*)d_in[2];
    const float* b1 = (const float*)d_in[3];
    const float* W2 = (const float*)d_in[4];
    const float* b2 = (const float*)d_in[5];
    float* out = (float*)d_out;

    // zero the combine target (out is poisoned); losses written by setup_kernel
    cudaMemsetAsync(out, 0, (size_t)T_TOK * D_DIM * sizeof(float));

    gate_kernel<<<T_TOK / 128, 128>>>(x, Wg);
    setup_kernel<<<1, 256>>>(out);
    scatter_kernel<<<(T_TOK + 255) / 256, 256>>>();

    dim3 g1(T_TOK / BM, H_DIM / BN, E_NUM);   // (64, 8, 8) worst-case; empty tiles exit
    gemm1_kernel<<<g1, 256>>>(x, W1, b1);

    dim3 g2(T_TOK / BM, D_DIM / BN, E_NUM);   // (64, 4, 8)
    gemm2_kernel<<<g2, 256>>>(W2, b2, out);
}

// round 5
// speedup vs baseline: 1.7118x; 1.7118x over previous
#include <cuda_runtime.h>
#include <cuda_bf16.h>
#include <cstdint>
#include <math.h>

// Problem constants (fixed shapes)
#define T_TOK 8192
#define D_DIM 512
#define H_DIM 1024
#define E_NUM 8
#define K_TOP 2
#define PAIRS (T_TOK * K_TOP)   // 16384

// GEMM tile config
#define BM 128
#define BN 128
#define BK 32
#define ROWU 18   // u32 stride per smem row (16 data + 2 pad)

// ---------------- device scratch (no allocations allowed) ----------------
__device__ uint32_t g_Hpack[(size_t)PAIRS * H_DIM];          // packed (hi|lo<<16) bf16 activations
__device__ uint32_t g_W1p[(size_t)E_NUM * H_DIM * D_DIM];    // W1 transposed [E][H][D], split-packed
__device__ uint32_t g_W2p[(size_t)E_NUM * D_DIM * H_DIM];    // W2 transposed [E][D][H], split-packed
__device__ int   g_e0[T_TOK], g_e1[T_TOK];
__device__ float g_g0[T_TOK], g_g1[T_TOK];
__device__ int   g_cnt[E_NUM], g_off[E_NUM], g_cursor[E_NUM];
__device__ int   g_tok[PAIRS];
__device__ float g_gate[PAIRS];

// fp32 -> (hi bf16 | lo bf16 << 16)
__device__ __forceinline__ uint32_t pack_hilo(float v) {
    __nv_bfloat16 h = __float2bfloat16(v);
    float hf = __bfloat162float(h);
    __nv_bfloat16 l = __float2bfloat16(v - hf);
    return (uint32_t)__bfloat16_as_ushort(h) | ((uint32_t)__bfloat16_as_ushort(l) << 16);
}
// two fp32 -> pair-packed bf16 hi reg and lo reg ({lo16 = elem j, hi16 = elem j+1})
__device__ __forceinline__ void split2(float a, float b, uint32_t& h, uint32_t& l) {
    uint32_t pa = pack_hilo(a), pb = pack_hilo(b);
    h = __byte_perm(pa, pb, 0x5410);
    l = __byte_perm(pa, pb, 0x7632);
}

// mma.sync m16n8k16 bf16 (row.col), fp32 accum
__device__ __forceinline__ void mma16816(float* c, const uint32_t* a, const uint32_t* b) {
    asm volatile(
        "mma.sync.aligned.m16n8k16.row.col.f32.bf16.bf16.f32 "
        "{%0,%1,%2,%3}, {%4,%5,%6,%7}, {%8,%9}, {%0,%1,%2,%3};\n"
        : "+f"(c[0]), "+f"(c[1]), "+f"(c[2]), "+f"(c[3])
        : "r"(a[0]), "r"(a[1]), "r"(a[2]), "r"(a[3]), "r"(b[0]), "r"(b[1]));
}

// ---------------- 1) gating: logits, top-2, softmax ----------------
__global__ void gate_kernel(const float* __restrict__ x,
                            const float* __restrict__ Wg) {
    __shared__ float xs[128][68];
    __shared__ float wgs[64][8];
    const int tid = threadIdx.x;
    const int t0  = blockIdx.x * 128;
    float acc[E_NUM];
#pragma unroll
    for (int e = 0; e < E_NUM; e++) acc[e] = 0.f;

    for (int k0 = 0; k0 < D_DIM; k0 += 64) {
#pragma unroll
        for (int i = 0; i < 4; i++) {
            int idx = tid + i * 128;
            wgs[idx >> 3][idx & 7] = Wg[(k0 + (idx >> 3)) * E_NUM + (idx & 7)];
        }
#pragma unroll
        for (int i = 0; i < 16; i++) {
            int f4  = i * 128 + tid;
            int row = f4 >> 4;
            int c4  = f4 & 15;
            float4 v = *(const float4*)(x + (size_t)(t0 + row) * D_DIM + k0 + c4 * 4);
            *(float4*)&xs[row][c4 * 4] = v;
        }
        __syncthreads();
#pragma unroll 8
        for (int k = 0; k < 64; k++) {
            float xv = xs[tid][k];
#pragma unroll
            for (int e = 0; e < E_NUM; e++) acc[e] = fmaf(xv, wgs[k][e], acc[e]);
        }
        __syncthreads();
    }
    int e0 = 0; float v0 = acc[0];
#pragma unroll
    for (int e = 1; e < E_NUM; e++) if (acc[e] > v0) { v0 = acc[e]; e0 = e; }
    int e1 = -1; float v1 = -INFINITY;
#pragma unroll
    for (int e = 0; e < E_NUM; e++) if (e != e0 && acc[e] > v1) { v1 = acc[e]; e1 = e; }
    float p1 = __expf(v1 - v0);
    float inv = 1.f / (1.f + p1);
    int t = t0 + tid;
    g_e0[t] = e0; g_e1[t] = e1;
    g_g0[t] = inv; g_g1[t] = p1 * inv;
}

// ---------------- 2) setup: reductions, offsets, losses ----------------
__global__ void setup_kernel(float* __restrict__ out) {
    __shared__ float simp[E_NUM][256];
    __shared__ int   scnt[E_NUM][256];
    const int tid = threadIdx.x;
    float imp[E_NUM]; int cnt[E_NUM];
#pragma unroll
    for (int e = 0; e < E_NUM; e++) { imp[e] = 0.f; cnt[e] = 0; }
    for (int t = tid; t < T_TOK; t += 256) {
        int a = g_e0[t]; imp[a] += g_g0[t]; cnt[a]++;
        int b = g_e1[t]; imp[b] += g_g1[t]; cnt[b]++;
    }
#pragma unroll
    for (int e = 0; e < E_NUM; e++) { simp[e][tid] = imp[e]; scnt[e][tid] = cnt[e]; }
    __syncthreads();
    for (int s = 128; s > 0; s >>= 1) {
        if (tid < s) {
#pragma unroll
            for (int e = 0; e < E_NUM; e++) {
                simp[e][tid] += simp[e][tid + s];
                scnt[e][tid] += scnt[e][tid + s];
            }
        }
        __syncthreads();
    }
    if (tid == 0) {
        const float eps = 1e-10f;
        int off = 0;
        float mi = 0.f, ml = 0.f;
#pragma unroll
        for (int e = 0; e < E_NUM; e++) {
            g_off[e] = off; g_cnt[e] = scnt[e][0]; g_cursor[e] = 0;
            off += scnt[e][0];
            mi += simp[e][0];
            ml += (float)scnt[e][0];
        }
        mi /= E_NUM; ml /= E_NUM;
        float vi = 0.f, vl = 0.f;
#pragma unroll
        for (int e = 0; e < E_NUM; e++) {
            float di = simp[e][0] - mi; vi += di * di;
            float dl = (float)scnt[e][0] - ml; vl += dl * dl;
        }
        vi /= (E_NUM - 1); vl /= (E_NUM - 1);
        out[(size_t)T_TOK * D_DIM]     = vi / (mi * mi + eps);
        out[(size_t)T_TOK * D_DIM + 1] = vl / (ml * ml + eps);
    }
}

// ---------------- 3) scatter ----------------
__global__ void scatter_kernel() {
    int t = blockIdx.x * 256 + threadIdx.x;
    if (t >= T_TOK) return;
    {
        int e = g_e0[t];
        int p = atomicAdd(&g_cursor[e], 1);
        int s = g_off[e] + p;
        g_tok[s] = t; g_gate[s] = g_g0[t];
    }
    {
        int e = g_e1[t];
        int p = atomicAdd(&g_cursor[e], 1);
        int s = g_off[e] + p;
        g_tok[s] = t; g_gate[s] = g_g1[t];
    }
}

// ------------- weight transpose + split-pack -------------
template <int R, int C>
__device__ __forceinline__ void transpose_pack(const float* __restrict__ s, uint32_t* __restrict__ d) {
    __shared__ float tile[32][33];
    int c0 = blockIdx.x * 32, r0 = blockIdx.y * 32;
#pragma unroll
    for (int i = 0; i < 32; i += 8)
        tile[threadIdx.y + i][threadIdx.x] = s[(size_t)(r0 + threadIdx.y + i) * C + c0 + threadIdx.x];
    __syncthreads();
#pragma unroll
    for (int i = 0; i < 32; i += 8) {
        float v = tile[threadIdx.x][threadIdx.y + i];
        d[(size_t)(c0 + threadIdx.y + i) * R + r0 + threadIdx.x] = pack_hilo(v);
    }
}
__global__ void conv_w1_kernel(const float* __restrict__ W1) {
    int e = blockIdx.z;
    transpose_pack<D_DIM, H_DIM>(W1 + (size_t)e * D_DIM * H_DIM, g_W1p + (size_t)e * D_DIM * H_DIM);
}
__global__ void conv_w2_kernel(const float* __restrict__ W2) {
    int e = blockIdx.z;
    transpose_pack<H_DIM, D_DIM>(W2 + (size_t)e * H_DIM * D_DIM, g_W2p + (size_t)e * H_DIM * D_DIM);
}

// ---------------- shared GEMM core (HMMA, 3-term bf16 split) ----------------
// smem tiles: rows of ROWU u32 (16 data u32 = 32 bf16)
struct SmemTiles {
    uint32_t Ah[BM * ROWU];
    uint32_t Al[BM * ROWU];
    uint32_t Bh[BN * ROWU];
    uint32_t Bl[BN * ROWU];
    int   toks[BM];
    float gates[BM];
    float bias[BN];
};

// run the k-loop; acc[mi][ni][r]
__device__ __forceinline__ void mma_loop_step(SmemTiles& sm, int wm, int wn, int g, int q,
                                              float acc[4][4][4]) {
#pragma unroll
    for (int s = 0; s < 2; s++) {
        uint32_t ah[4][4], al[4][4];
#pragma unroll
        for (int mi = 0; mi < 4; mi++) {
            int r0 = (wm * 64 + mi * 16 + g) * ROWU + s * 8 + q;
            int r8 = r0 + 8 * ROWU;
            ah[mi][0] = sm.Ah[r0];     ah[mi][1] = sm.Ah[r8];
            ah[mi][2] = sm.Ah[r0 + 4]; ah[mi][3] = sm.Ah[r8 + 4];
            al[mi][0] = sm.Al[r0];     al[mi][1] = sm.Al[r8];
            al[mi][2] = sm.Al[r0 + 4]; al[mi][3] = sm.Al[r8 + 4];
        }
#pragma unroll
        for (int ni = 0; ni < 4; ni++) {
            int b0 = (wn * 32 + ni * 8 + g) * ROWU + s * 8 + q;
            uint32_t bh[2] = { sm.Bh[b0], sm.Bh[b0 + 4] };
            uint32_t bl[2] = { sm.Bl[b0], sm.Bl[b0 + 4] };
#pragma unroll
            for (int mi = 0; mi < 4; mi++) {
                mma16816(acc[mi][ni], ah[mi], bh);
                mma16816(acc[mi][ni], ah[mi], bl);
                mma16816(acc[mi][ni], al[mi], bh);
            }
        }
    }
}

// ---------------- 4) GEMM1: H = relu(gather(x) @ W1 + b1) ----------------
__global__ __launch_bounds__(256, 2)
void gemm1_mma(const float* __restrict__ x, const float* __restrict__ b1) {
    __shared__ SmemTiles sm;
    const int e   = blockIdx.z;
    const int cnt = g_cnt[e];
    const int m0  = blockIdx.x * BM;
    if (m0 >= cnt) return;
    const int n0   = blockIdx.y * BN;
    const int off  = g_off[e];
    const int mrem = cnt - m0;
    const int tid  = threadIdx.x;
    const int wid  = tid >> 5, lid = tid & 31;
    const int wm = wid >> 2, wn = wid & 3;
    const int g = lid >> 2, q = lid & 3;

    if (tid < BM) {
        sm.toks[tid] = (tid < mrem) ? g_tok[off + m0 + tid] : -1;
        sm.bias[tid] = b1[(size_t)e * H_DIM + n0 + tid];
    }
    __syncthreads();

    float acc[4][4][4];
#pragma unroll
    for (int a = 0; a < 4; a++)
#pragma unroll
        for (int b = 0; b < 4; b++)
#pragma unroll
            for (int c = 0; c < 4; c++) acc[a][b][c] = 0.f;

    const uint32_t* Bsrc = g_W1p + ((size_t)e * H_DIM + n0) * D_DIM;

    for (int k0 = 0; k0 < D_DIM; k0 += BK) {
        if (k0) __syncthreads();
        // A: gather fp32 -> split pairs
#pragma unroll
        for (int i = 0; i < 4; i++) {
            int idx = tid + i * 256;         // 1024 float4
            int row = idx >> 3, c4 = idx & 7;
            int tok = sm.toks[row];
            float4 v = make_float4(0.f, 0.f, 0.f, 0.f);
            if (tok >= 0) v = *(const float4*)(x + (size_t)tok * D_DIM + k0 + c4 * 4);
            uint32_t h0, l0, h1, l1;
            split2(v.x, v.y, h0, l0);
            split2(v.z, v.w, h1, l1);
            int o = row * ROWU + c4 * 2;
            sm.Ah[o] = h0; sm.Ah[o + 1] = h1;
            sm.Al[o] = l0; sm.Al[o + 1] = l1;
        }
        // B: pre-packed u32 per element
#pragma unroll
        for (int i = 0; i < 4; i++) {
            int idx = tid + i * 256;
            int row = idx >> 3, c4 = idx & 7;
            uint4 p = *(const uint4*)(Bsrc + (size_t)row * D_DIM + k0 + c4 * 4);
            int o = row * ROWU + c4 * 2;
            sm.Bh[o]     = __byte_perm(p.x, p.y, 0x5410);
            sm.Bl[o]     = __byte_perm(p.x, p.y, 0x7632);
            sm.Bh[o + 1] = __byte_perm(p.z, p.w, 0x5410);
            sm.Bl[o + 1] = __byte_perm(p.z, p.w, 0x7632);
        }
        __syncthreads();
        mma_loop_step(sm, wm, wn, g, q, acc);
    }

    // epilogue: bias + relu -> packed H
#pragma unroll
    for (int mi = 0; mi < 4; mi++) {
#pragma unroll
        for (int h = 0; h < 2; h++) {
            int mrow = wm * 64 + mi * 16 + g + h * 8;
            if (mrow < mrem) {
                uint32_t* dst = g_Hpack + (size_t)(off + m0 + mrow) * H_DIM + n0;
#pragma unroll
                for (int ni = 0; ni < 4; ni++) {
                    int n = wn * 32 + ni * 8 + q * 2;
                    float v0 = fmaxf(acc[mi][ni][h * 2 + 0] + sm.bias[n], 0.f);
                    float v1 = fmaxf(acc[mi][ni][h * 2 + 1] + sm.bias[n + 1], 0.f);
                    uint2 pw = make_uint2(pack_hilo(v0), pack_hilo(v1));
                    *(uint2*)(dst + n) = pw;
                }
            }
        }
    }
}

// ---------------- 5) GEMM2: out += gate * (H @ W2 + b2) ----------------
__global__ __launch_bounds__(256, 2)
void gemm2_mma(const float* __restrict__ b2, float* __restrict__ out) {
    __shared__ SmemTiles sm;
    const int e   = blockIdx.z;
    const int cnt = g_cnt[e];
    const int m0  = blockIdx.x * BM;
    if (m0 >= cnt) return;
    const int n0   = blockIdx.y * BN;
    const int off  = g_off[e];
    const int mrem = cnt - m0;
    const int tid  = threadIdx.x;
    const int wid  = tid >> 5, lid = tid & 31;
    const int wm = wid >> 2, wn = wid & 3;
    const int g = lid >> 2, q = lid & 3;

    if (tid < BM) {
        int valid = tid < mrem;
        int s = off + m0 + tid;
        sm.toks[tid]  = valid ? g_tok[s] : -1;
        sm.gates[tid] = valid ? g_gate[s] : 0.f;
        sm.bias[tid]  = b2[(size_t)e * D_DIM + n0 + tid];
    }
    __syncthreads();

    float acc[4][4][4];
#pragma unroll
    for (int a = 0; a < 4; a++)
#pragma unroll
        for (int b = 0; b < 4; b++)
#pragma unroll
            for (int c = 0; c < 4; c++) acc[a][b][c] = 0.f;

    const uint32_t* Asrc = g_Hpack + (size_t)(off + m0) * H_DIM;
    const uint32_t* Bsrc = g_W2p + ((size_t)e * D_DIM + n0) * H_DIM;

    for (int k0 = 0; k0 < H_DIM; k0 += BK) {
        if (k0) __syncthreads();
        // A: packed activations
#pragma unroll
        for (int i = 0; i < 4; i++) {
            int idx = tid + i * 256;
            int row = idx >> 3, c4 = idx & 7;
            uint4 p = make_uint4(0u, 0u, 0u, 0u);
            if (row < mrem) p = *(const uint4*)(Asrc + (size_t)row * H_DIM + k0 + c4 * 4);
            int o = row * ROWU + c4 * 2;
            sm.Ah[o]     = __byte_perm(p.x, p.y, 0x5410);
            sm.Al[o]     = __byte_perm(p.x, p.y, 0x7632);
            sm.Ah[o + 1] = __byte_perm(p.z, p.w, 0x5410);
            sm.Al[o + 1] = __byte_perm(p.z, p.w, 0x7632);
        }
        // B
#pragma unroll
        for (int i = 0; i < 4; i++) {
            int idx = tid + i * 256;
            int row = idx >> 3, c4 = idx & 7;
            uint4 p = *(const uint4*)(Bsrc + (size_t)row * H_DIM + k0 + c4 * 4);
            int o = row * ROWU + c4 * 2;
            sm.Bh[o]     = __byte_perm(p.x, p.y, 0x5410);
            sm.Bl[o]     = __byte_perm(p.x, p.y, 0x7632);
            sm.Bh[o + 1] = __byte_perm(p.z, p.w, 0x5410);
            sm.Bl[o + 1] = __byte_perm(p.z, p.w, 0x7632);
        }
        __syncthreads();
        mma_loop_step(sm, wm, wn, g, q, acc);
    }

    // epilogue: (acc + bias) * gate -> atomicAdd combine
#pragma unroll
    for (int mi = 0; mi < 4; mi++) {
#pragma unroll
        for (int h = 0; h < 2; h++) {
            int mrow = wm * 64 + mi * 16 + g + h * 8;
            if (mrow < mrem) {
                int tok  = sm.toks[mrow];
                float gt = sm.gates[mrow];
                float* dst = out + (size_t)tok * D_DIM + n0;
#pragma unroll
                for (int ni = 0; ni < 4; ni++) {
                    int n = wn * 32 + ni * 8 + q * 2;
                    atomicAdd(&dst[n],     (acc[mi][ni][h * 2 + 0] + sm.bias[n]) * gt);
                    atomicAdd(&dst[n + 1], (acc[mi][ni][h * 2 + 1] + sm.bias[n + 1]) * gt);
                }
            }
        }
    }
}

// ---------------- launch ----------------
extern "C" void kernel_launch(void* const* d_in, const int* in_sizes, int n_in,
                              void* d_out, int out_size) {
    const float* x  = (const float*)d_in[0];
    const float* Wg = (const float*)d_in[1];
    const float* W1 = (const float*)d_in[2];
    const float* b1 = (const float*)d_in[3];
    const float* W2 = (const float*)d_in[4];
    const float* b2 = (const float*)d_in[5];
    float* out = (float*)d_out;

    cudaMemsetAsync(out, 0, (size_t)T_TOK * D_DIM * sizeof(float));

    gate_kernel<<<T_TOK / 128, 128>>>(x, Wg);
    setup_kernel<<<1, 256>>>(out);
    scatter_kernel<<<(T_TOK + 255) / 256, 256>>>();

    conv_w1_kernel<<<dim3(H_DIM / 32, D_DIM / 32, E_NUM), dim3(32, 8)>>>(W1);
    conv_w2_kernel<<<dim3(D_DIM / 32, H_DIM / 32, E_NUM), dim3(32, 8)>>>(W2);

    dim3 g1(T_TOK / BM, H_DIM / BN, E_NUM);   // (64, 8, 8), empty tiles exit
    gemm1_mma<<<g1, 256>>>(x, b1);

    dim3 g2(T_TOK / BM, D_DIM / BN, E_NUM);   // (64, 4, 8)
    gemm2_mma<<<g2, 256>>>(b2, out);
}

// round 6
// speedup vs baseline: 2.4555x; 1.4345x over previous
#include <cuda_runtime.h>
#include <cuda_bf16.h>
#include <cstdint>
#include <math.h>

// Problem constants (fixed shapes)
#define T_TOK 8192
#define D_DIM 512
#define H_DIM 1024
#define E_NUM 8
#define K_TOP 2
#define PAIRS (T_TOK * K_TOP)   // 16384

// GEMM tile config
#define BM 128
#define BN 128
#define BK 32
#define TILE_U16 (BM * BK)      // 4096 u16 per plane tile

// ---------------- device scratch (no allocations allowed) ----------------
__device__ uint16_t g_Xh[(size_t)T_TOK * D_DIM];             // x split planes (bf16 bits)
__device__ uint16_t g_Xl[(size_t)T_TOK * D_DIM];
__device__ uint16_t g_Hh[(size_t)PAIRS * H_DIM];             // activations split planes
__device__ uint16_t g_Hl[(size_t)PAIRS * H_DIM];
__device__ uint16_t g_W1h[(size_t)E_NUM * H_DIM * D_DIM];    // W1^T [E][H][D] planes
__device__ uint16_t g_W1l[(size_t)E_NUM * H_DIM * D_DIM];
__device__ uint16_t g_W2h[(size_t)E_NUM * D_DIM * H_DIM];    // W2^T [E][D][H] planes
__device__ uint16_t g_W2l[(size_t)E_NUM * D_DIM * H_DIM];
__device__ int   g_e0[T_TOK], g_e1[T_TOK];
__device__ float g_g0[T_TOK], g_g1[T_TOK];
__device__ int   g_cnt[E_NUM], g_off[E_NUM], g_cursor[E_NUM];
__device__ int   g_tok[PAIRS];
__device__ float g_gate[PAIRS];

// ---------------- helpers ----------------
__device__ __forceinline__ uint32_t smem_u32(const void* p) {
    uint32_t a;
    asm("{ .reg .u64 t; cvta.to.shared.u64 t, %1; cvt.u32.u64 %0, t; }" : "=r"(a) : "l"(p));
    return a;
}
// fp32 -> bf16 hi bits and lo bits (v ~= hi + lo)
__device__ __forceinline__ void split1(float v, uint16_t& h, uint16_t& l) {
    __nv_bfloat16 bh = __float2bfloat16(v);
    float hf = __bfloat162float(bh);
    __nv_bfloat16 bl = __float2bfloat16(v - hf);
    h = __bfloat16_as_ushort(bh);
    l = __bfloat16_as_ushort(bl);
}
__device__ __forceinline__ uint32_t pack2(uint16_t a, uint16_t b) {
    return (uint32_t)a | ((uint32_t)b << 16);
}

// mma.sync m16n8k16 bf16 (row.col), fp32 accum
__device__ __forceinline__ void mma16816(float* c, const uint32_t* a, const uint32_t* b) {
    asm volatile(
        "mma.sync.aligned.m16n8k16.row.col.f32.bf16.bf16.f32 "
        "{%0,%1,%2,%3}, {%4,%5,%6,%7}, {%8,%9}, {%0,%1,%2,%3};\n"
        : "+f"(c[0]), "+f"(c[1]), "+f"(c[2]), "+f"(c[3])
        : "r"(a[0]), "r"(a[1]), "r"(a[2]), "r"(a[3]), "r"(b[0]), "r"(b[1]));
}
__device__ __forceinline__ void ldsm4(uint32_t* r, uint32_t a) {
    asm volatile("ldmatrix.sync.aligned.m8n8.x4.shared.b16 {%0,%1,%2,%3}, [%4];"
        : "=r"(r[0]), "=r"(r[1]), "=r"(r[2]), "=r"(r[3]) : "r"(a));
}
__device__ __forceinline__ void cpa16(uint32_t dst, const void* src, int srcsz) {
    asm volatile("cp.async.cg.shared.global [%0], [%1], 16, %2;"
        :: "r"(dst), "l"(src), "r"(srcsz) : "memory");
}
#define CP_COMMIT() asm volatile("cp.async.commit_group;" ::: "memory")
#define CP_WAIT(n)  asm volatile("cp.async.wait_group %0;" :: "n"(n) : "memory")

// smem tile byte offset for (row, seg) with XOR swizzle; seg = 16B segment (0..3)
__device__ __forceinline__ uint32_t sw_off(int row, int seg) {
    return (uint32_t)(row * 64 + ((seg ^ ((row >> 1) & 3)) << 4));
}

// ---------------- 1) gating: logits, top-2, softmax; also emits x planes ----
__global__ void gate_kernel(const float* __restrict__ x,
                            const float* __restrict__ Wg) {
    __shared__ float xs[128][68];
    __shared__ float wgs[64][8];
    const int tid = threadIdx.x;
    const int t0  = blockIdx.x * 128;
    float acc[E_NUM];
#pragma unroll
    for (int e = 0; e < E_NUM; e++) acc[e] = 0.f;

    for (int k0 = 0; k0 < D_DIM; k0 += 64) {
#pragma unroll
        for (int i = 0; i < 4; i++) {
            int idx = tid + i * 128;
            wgs[idx >> 3][idx & 7] = Wg[(k0 + (idx >> 3)) * E_NUM + (idx & 7)];
        }
#pragma unroll
        for (int i = 0; i < 16; i++) {
            int f4  = i * 128 + tid;
            int row = f4 >> 4;
            int c4  = f4 & 15;
            float4 v = *(const float4*)(x + (size_t)(t0 + row) * D_DIM + k0 + c4 * 4);
            *(float4*)&xs[row][c4 * 4] = v;
            // emit split planes (same coalesced pattern)
            uint16_t h0,l0,h1,l1,h2,l2,h3,l3;
            split1(v.x, h0, l0); split1(v.y, h1, l1);
            split1(v.z, h2, l2); split1(v.w, h3, l3);
            size_t o = (size_t)(t0 + row) * D_DIM + k0 + c4 * 4;
            *(uint2*)(g_Xh + o) = make_uint2(pack2(h0, h1), pack2(h2, h3));
            *(uint2*)(g_Xl + o) = make_uint2(pack2(l0, l1), pack2(l2, l3));
        }
        __syncthreads();
#pragma unroll 8
        for (int k = 0; k < 64; k++) {
            float xv = xs[tid][k];
#pragma unroll
            for (int e = 0; e < E_NUM; e++) acc[e] = fmaf(xv, wgs[k][e], acc[e]);
        }
        __syncthreads();
    }
    int e0 = 0; float v0 = acc[0];
#pragma unroll
    for (int e = 1; e < E_NUM; e++) if (acc[e] > v0) { v0 = acc[e]; e0 = e; }
    int e1 = -1; float v1 = -INFINITY;
#pragma unroll
    for (int e = 0; e < E_NUM; e++) if (e != e0 && acc[e] > v1) { v1 = acc[e]; e1 = e; }
    float p1 = __expf(v1 - v0);
    float inv = 1.f / (1.f + p1);
    int t = t0 + tid;
    g_e0[t] = e0; g_e1[t] = e1;
    g_g0[t] = inv; g_g1[t] = p1 * inv;
}

// ---------------- 2) setup: reductions, offsets, losses ----------------
__global__ void setup_kernel(float* __restrict__ out) {
    __shared__ float simp[E_NUM][256];
    __shared__ int   scnt[E_NUM][256];
    const int tid = threadIdx.x;
    float imp[E_NUM]; int cnt[E_NUM];
#pragma unroll
    for (int e = 0; e < E_NUM; e++) { imp[e] = 0.f; cnt[e] = 0; }
    for (int t = tid; t < T_TOK; t += 256) {
        int a = g_e0[t]; imp[a] += g_g0[t]; cnt[a]++;
        int b = g_e1[t]; imp[b] += g_g1[t]; cnt[b]++;
    }
#pragma unroll
    for (int e = 0; e < E_NUM; e++) { simp[e][tid] = imp[e]; scnt[e][tid] = cnt[e]; }
    __syncthreads();
    for (int s = 128; s > 0; s >>= 1) {
        if (tid < s) {
#pragma unroll
            for (int e = 0; e < E_NUM; e++) {
                simp[e][tid] += simp[e][tid + s];
                scnt[e][tid] += scnt[e][tid + s];
            }
        }
        __syncthreads();
    }
    if (tid == 0) {
        const float eps = 1e-10f;
        int off = 0;
        float mi = 0.f, ml = 0.f;
#pragma unroll
        for (int e = 0; e < E_NUM; e++) {
            g_off[e] = off; g_cnt[e] = scnt[e][0]; g_cursor[e] = 0;
            off += scnt[e][0];
            mi += simp[e][0];
            ml += (float)scnt[e][0];
        }
        mi /= E_NUM; ml /= E_NUM;
        float vi = 0.f, vl = 0.f;
#pragma unroll
        for (int e = 0; e < E_NUM; e++) {
            float di = simp[e][0] - mi; vi += di * di;
            float dl = (float)scnt[e][0] - ml; vl += dl * dl;
        }
        vi /= (E_NUM - 1); vl /= (E_NUM - 1);
        out[(size_t)T_TOK * D_DIM]     = vi / (mi * mi + eps);
        out[(size_t)T_TOK * D_DIM + 1] = vl / (ml * ml + eps);
    }
}

// ---------------- 3) scatter ----------------
__global__ void scatter_kernel() {
    int t = blockIdx.x * 256 + threadIdx.x;
    if (t >= T_TOK) return;
    {
        int e = g_e0[t];
        int p = atomicAdd(&g_cursor[e], 1);
        int s = g_off[e] + p;
        g_tok[s] = t; g_gate[s] = g_g0[t];
    }
    {
        int e = g_e1[t];
        int p = atomicAdd(&g_cursor[e], 1);
        int s = g_off[e] + p;
        g_tok[s] = t; g_gate[s] = g_g1[t];
    }
}

// ------------- weight transpose + split into planes -------------
template <int R, int C>
__device__ __forceinline__ void transpose_split(const float* __restrict__ s,
                                                uint16_t* __restrict__ dh,
                                                uint16_t* __restrict__ dl) {
    __shared__ float tile[32][33];
    int c0 = blockIdx.x * 32, r0 = blockIdx.y * 32;
#pragma unroll
    for (int i = 0; i < 32; i += 8)
        tile[threadIdx.y + i][threadIdx.x] = s[(size_t)(r0 + threadIdx.y + i) * C + c0 + threadIdx.x];
    __syncthreads();
#pragma unroll
    for (int i = 0; i < 32; i += 8) {
        float v = tile[threadIdx.x][threadIdx.y + i];
        uint16_t h, l; split1(v, h, l);
        size_t o = (size_t)(c0 + threadIdx.y + i) * R + r0 + threadIdx.x;
        dh[o] = h; dl[o] = l;
    }
}
__global__ void conv_w1_kernel(const float* __restrict__ W1) {
    int e = blockIdx.z;
    size_t eo = (size_t)e * D_DIM * H_DIM;
    transpose_split<D_DIM, H_DIM>(W1 + eo, g_W1h + eo, g_W1l + eo);
}
__global__ void conv_w2_kernel(const float* __restrict__ W2) {
    int e = blockIdx.z;
    size_t eo = (size_t)e * H_DIM * D_DIM;
    transpose_split<H_DIM, D_DIM>(W2 + eo, g_W2h + eo, g_W2l + eo);
}

// ---------------- shared GEMM smem ----------------
struct GS {
    uint16_t Ah[2][TILE_U16];
    uint16_t Al[2][TILE_U16];
    uint16_t Bh[2][TILE_U16];
    uint16_t Bl[2][TILE_U16];
    int   toks[BM];
    float gates[BM];
    float bias[BN];
};
#define GS_BYTES sizeof(GS)

// compute one k32 chunk from stage st
__device__ __forceinline__ void compute_chunk(GS* gs, int st, int wm, int wn, int lid,
                                              float acc[4][4][4]) {
    const int r_ = lid & 7, mat = lid >> 3;
    uint32_t pAh = smem_u32(gs->Ah[st]), pAl = smem_u32(gs->Al[st]);
    uint32_t pBh = smem_u32(gs->Bh[st]), pBl = smem_u32(gs->Bl[st]);
#pragma unroll
    for (int s = 0; s < 2; s++) {
        uint32_t bh[4][2], bl[4][2];
#pragma unroll
        for (int np = 0; np < 2; np++) {
            int row = wn * 32 + np * 16 + ((mat >> 1) << 3) + r_;
            int colseg = (s << 1) | (mat & 1);
            uint32_t o = sw_off(row, colseg);
            uint32_t t[4];
            ldsm4(t, pBh + o);
            bh[np*2][0] = t[0]; bh[np*2][1] = t[1];
            bh[np*2+1][0] = t[2]; bh[np*2+1][1] = t[3];
            ldsm4(t, pBl + o);
            bl[np*2][0] = t[0]; bl[np*2][1] = t[1];
            bl[np*2+1][0] = t[2]; bl[np*2+1][1] = t[3];
        }
#pragma unroll
        for (int mi = 0; mi < 4; mi++) {
            int row = wm * 64 + mi * 16 + ((mat & 1) << 3) + r_;
            int colseg = (s << 1) | (mat >> 1);
            uint32_t o = sw_off(row, colseg);
            uint32_t ah[4], al[4];
            ldsm4(ah, pAh + o);
            ldsm4(al, pAl + o);
#pragma unroll
            for (int ni = 0; ni < 4; ni++) {
                mma16816(acc[mi][ni], ah, bh[ni]);
                mma16816(acc[mi][ni], ah, bl[ni]);
                mma16816(acc[mi][ni], al, bh[ni]);
            }
        }
    }
}

// fill one stage: A gathered by tok list (LD = lda), B linear (LD = ldb)
__device__ __forceinline__ void fill_stage(GS* gs, int st, int tid,
                                           const uint16_t* __restrict__ Ah, const uint16_t* __restrict__ Al,
                                           const uint16_t* __restrict__ Bh, const uint16_t* __restrict__ Bl,
                                           int k0, int lda, int ldb, bool gatherA, int mrem) {
    uint32_t pAh = smem_u32(gs->Ah[st]), pAl = smem_u32(gs->Al[st]);
    uint32_t pBh = smem_u32(gs->Bh[st]), pBl = smem_u32(gs->Bl[st]);
#pragma unroll
    for (int i = 0; i < 2; i++) {
        int id  = tid + i * 256;   // 0..511
        int row = id >> 2, seg = id & 3;
        uint32_t d = sw_off(row, seg);
        // A (possibly gathered, possibly invalid row)
        int vs; size_t grow;
        if (gatherA) {
            int tok = gs->toks[row];
            vs = (tok >= 0) ? 16 : 0;
            grow = (tok >= 0) ? (size_t)tok : 0;
        } else {
            vs = (row < mrem) ? 16 : 0;
            grow = (row < mrem) ? (size_t)row : 0;
        }
        size_t ao = grow * lda + k0 + seg * 8;
        cpa16(pAh + d, Ah + ao, vs);
        cpa16(pAl + d, Al + ao, vs);
        // B (always valid)
        size_t bo = (size_t)row * ldb + k0 + seg * 8;
        cpa16(pBh + d, Bh + bo, 16);
        cpa16(pBl + d, Bl + bo, 16);
    }
}

// ---------------- 4) GEMM1: H = relu(gather(x) @ W1 + b1) ----------------
__global__ __launch_bounds__(256, 2)
void gemm1_mma(const float* __restrict__ b1) {
    extern __shared__ __align__(16) char smraw[];
    GS* gs = (GS*)smraw;
    const int e   = blockIdx.z;
    const int cnt = g_cnt[e];
    const int m0  = blockIdx.x * BM;
    if (m0 >= cnt) return;
    const int n0   = blockIdx.y * BN;
    const int off  = g_off[e];
    const int mrem = cnt - m0;
    const int tid  = threadIdx.x;
    const int wid  = tid >> 5, lid = tid & 31;
    const int wm = wid >> 2, wn = wid & 3;
    const int g = lid >> 2, q = lid & 3;

    if (tid < BM) {
        gs->toks[tid] = (tid < mrem) ? g_tok[off + m0 + tid] : -1;
        gs->bias[tid] = b1[(size_t)e * H_DIM + n0 + tid];
    }
    __syncthreads();

    float acc[4][4][4];
#pragma unroll
    for (int a = 0; a < 4; a++)
#pragma unroll
        for (int b = 0; b < 4; b++)
#pragma unroll
            for (int c = 0; c < 4; c++) acc[a][b][c] = 0.f;

    const uint16_t* Bh = g_W1h + ((size_t)e * H_DIM + n0) * D_DIM;
    const uint16_t* Bl = g_W1l + ((size_t)e * H_DIM + n0) * D_DIM;

    const int NC = D_DIM / BK;   // 16
    fill_stage(gs, 0, tid, g_Xh, g_Xl, Bh, Bl, 0, D_DIM, D_DIM, true, mrem);
    CP_COMMIT();
    for (int c = 0; c < NC; c++) {
        int st = c & 1;
        if (c + 1 < NC) {
            fill_stage(gs, st ^ 1, tid, g_Xh, g_Xl, Bh, Bl, (c + 1) * BK, D_DIM, D_DIM, true, mrem);
            CP_COMMIT();
            CP_WAIT(1);
        } else {
            CP_WAIT(0);
        }
        __syncthreads();
        compute_chunk(gs, st, wm, wn, lid, acc);
        __syncthreads();
    }

    // epilogue: bias + relu -> split planes
#pragma unroll
    for (int mi = 0; mi < 4; mi++) {
#pragma unroll
        for (int h = 0; h < 2; h++) {
            int mrow = wm * 64 + mi * 16 + g + h * 8;
            if (mrow < mrem) {
                size_t rb = (size_t)(off + m0 + mrow) * H_DIM + n0;
#pragma unroll
                for (int ni = 0; ni < 4; ni++) {
                    int n = wn * 32 + ni * 8 + q * 2;
                    float v0 = fmaxf(acc[mi][ni][h * 2 + 0] + gs->bias[n], 0.f);
                    float v1 = fmaxf(acc[mi][ni][h * 2 + 1] + gs->bias[n + 1], 0.f);
                    uint16_t h0, l0, h1, l1;
                    split1(v0, h0, l0); split1(v1, h1, l1);
                    *(uint32_t*)(g_Hh + rb + n) = pack2(h0, h1);
                    *(uint32_t*)(g_Hl + rb + n) = pack2(l0, l1);
                }
            }
        }
    }
}

// ---------------- 5) GEMM2: out += gate * (H @ W2 + b2) ----------------
__global__ __launch_bounds__(256, 2)
void gemm2_mma(const float* __restrict__ b2, float* __restrict__ out) {
    extern __shared__ __align__(16) char smraw[];
    GS* gs = (GS*)smraw;
    const int e   = blockIdx.z;
    const int cnt = g_cnt[e];
    const int m0  = blockIdx.x * BM;
    if (m0 >= cnt) return;
    const int n0   = blockIdx.y * BN;
    const int off  = g_off[e];
    const int mrem = cnt - m0;
    const int tid  = threadIdx.x;
    const int wid  = tid >> 5, lid = tid & 31;
    const int wm = wid >> 2, wn = wid & 3;
    const int g = lid >> 2, q = lid & 3;

    if (tid < BM) {
        int valid = tid < mrem;
        int s = off + m0 + tid;
        gs->toks[tid]  = valid ? g_tok[s] : -1;
        gs->gates[tid] = valid ? g_gate[s] : 0.f;
        gs->bias[tid]  = b2[(size_t)e * D_DIM + n0 + tid];
    }
    __syncthreads();

    float acc[4][4][4];
#pragma unroll
    for (int a = 0; a < 4; a++)
#pragma unroll
        for (int b = 0; b < 4; b++)
#pragma unroll
            for (int c = 0; c < 4; c++) acc[a][b][c] = 0.f;

    const uint16_t* Ahp = g_Hh + (size_t)(off + m0) * H_DIM;
    const uint16_t* Alp = g_Hl + (size_t)(off + m0) * H_DIM;
    const uint16_t* Bh  = g_W2h + ((size_t)e * D_DIM + n0) * H_DIM;
    const uint16_t* Bl  = g_W2l + ((size_t)e * D_DIM + n0) * H_DIM;

    const int NC = H_DIM / BK;   // 32
    fill_stage(gs, 0, tid, Ahp, Alp, Bh, Bl, 0, H_DIM, H_DIM, false, mrem);
    CP_COMMIT();
    for (int c = 0; c < NC; c++) {
        int st = c & 1;
        if (c + 1 < NC) {
            fill_stage(gs, st ^ 1, tid, Ahp, Alp, Bh, Bl, (c + 1) * BK, H_DIM, H_DIM, false, mrem);
            CP_COMMIT();
            CP_WAIT(1);
        } else {
            CP_WAIT(0);
        }
        __syncthreads();
        compute_chunk(gs, st, wm, wn, lid, acc);
        __syncthreads();
    }

    // epilogue: (acc + bias) * gate -> atomicAdd combine
#pragma unroll
    for (int mi = 0; mi < 4; mi++) {
#pragma unroll
        for (int h = 0; h < 2; h++) {
            int mrow = wm * 64 + mi * 16 + g + h * 8;
            if (mrow < mrem) {
                int tok  = gs->toks[mrow];
                float gt = gs->gates[mrow];
                float* dst = out + (size_t)tok * D_DIM + n0;
#pragma unroll
                for (int ni = 0; ni < 4; ni++) {
                    int n = wn * 32 + ni * 8 + q * 2;
                    atomicAdd(&dst[n],     (acc[mi][ni][h * 2 + 0] + gs->bias[n]) * gt);
                    atomicAdd(&dst[n + 1], (acc[mi][ni][h * 2 + 1] + gs->bias[n + 1]) * gt);
                }
            }
        }
    }
}

// ---------------- launch ----------------
extern "C" void kernel_launch(void* const* d_in, const int* in_sizes, int n_in,
                              void* d_out, int out_size) {
    const float* x  = (const float*)d_in[0];
    const float* Wg = (const float*)d_in[1];
    const float* W1 = (const float*)d_in[2];
    const float* b1 = (const float*)d_in[3];
    const float* W2 = (const float*)d_in[4];
    const float* b2 = (const float*)d_in[5];
    float* out = (float*)d_out;

    static bool attr_done = false;
    if (!attr_done) {
        cudaFuncSetAttribute(gemm1_mma, cudaFuncAttributeMaxDynamicSharedMemorySize, (int)GS_BYTES);
        cudaFuncSetAttribute(gemm2_mma, cudaFuncAttributeMaxDynamicSharedMemorySize, (int)GS_BYTES);
        attr_done = true;
    }

    cudaMemsetAsync(out, 0, (size_t)T_TOK * D_DIM * sizeof(float));

    gate_kernel<<<T_TOK / 128, 128>>>(x, Wg);
    setup_kernel<<<1, 256>>>(out);
    scatter_kernel<<<(T_TOK + 255) / 256, 256>>>();

    conv_w1_kernel<<<dim3(H_DIM / 32, D_DIM / 32, E_NUM), dim3(32, 8)>>>(W1);
    conv_w2_kernel<<<dim3(D_DIM / 32, H_DIM / 32, E_NUM), dim3(32, 8)>>>(W2);

    dim3 g1(T_TOK / BM, H_DIM / BN, E_NUM);   // (64, 8, 8), empty tiles exit
    gemm1_mma<<<g1, 256, GS_BYTES>>>(b1);

    dim3 g2(T_TOK / BM, D_DIM / BN, E_NUM);   // (64, 4, 8)
    gemm2_mma<<<g2, 256, GS_BYTES>>>(b2, out);
}

// round 7
// speedup vs baseline: 4.6304x; 1.8857x over previous
#include <cuda_runtime.h>
#include <cuda_bf16.h>
#include <cuda_fp16.h>
#include <cstdint>
#include <math.h>

// Problem constants (fixed shapes)
#define T_TOK 8192
#define D_DIM 512
#define H_DIM 1024
#define E_NUM 8
#define K_TOP 2
#define PAIRS (T_TOK * K_TOP)   // 16384

// GEMM tile config
#define BM 128
#define BN 128
#define BK 64
#define TILE_U16 (BM * BK)      // 8192 fp16 per tile (16KB)

// ---------------- device scratch (no allocations allowed) ----------------
__device__ uint16_t g_Xf[(size_t)T_TOK * D_DIM];             // x as fp16 bits
__device__ uint16_t g_Hf[(size_t)PAIRS * H_DIM];             // activations fp16
__device__ uint16_t g_W1f[(size_t)E_NUM * H_DIM * D_DIM];    // W1^T [E][H][D] fp16
__device__ uint16_t g_W2f[(size_t)E_NUM * D_DIM * H_DIM];    // W2^T [E][D][H] fp16
__device__ int   g_e0[T_TOK], g_e1[T_TOK];
__device__ float g_g0[T_TOK], g_g1[T_TOK];
__device__ int   g_cnt[E_NUM], g_off[E_NUM], g_cursor[E_NUM];
__device__ int   g_tok[PAIRS];
__device__ float g_gate[PAIRS];

// ---------------- helpers ----------------
__device__ __forceinline__ uint32_t smem_u32(const void* p) {
    uint32_t a;
    asm("{ .reg .u64 t; cvta.to.shared.u64 t, %1; cvt.u32.u64 %0, t; }" : "=r"(a) : "l"(p));
    return a;
}
__device__ __forceinline__ uint32_t packh2(float a, float b) {
    __half2 h = __floats2half2_rn(a, b);
    return *(uint32_t*)&h;
}

// mma.sync m16n8k16 fp16 (row.col), fp32 accum
__device__ __forceinline__ void mma16816(float* c, const uint32_t* a, const uint32_t* b) {
    asm volatile(
        "mma.sync.aligned.m16n8k16.row.col.f32.f16.f16.f32 "
        "{%0,%1,%2,%3}, {%4,%5,%6,%7}, {%8,%9}, {%0,%1,%2,%3};\n"
        : "+f"(c[0]), "+f"(c[1]), "+f"(c[2]), "+f"(c[3])
        : "r"(a[0]), "r"(a[1]), "r"(a[2]), "r"(a[3]), "r"(b[0]), "r"(b[1]));
}
__device__ __forceinline__ void ldsm4(uint32_t* r, uint32_t a) {
    asm volatile("ldmatrix.sync.aligned.m8n8.x4.shared.b16 {%0,%1,%2,%3}, [%4];"
        : "=r"(r[0]), "=r"(r[1]), "=r"(r[2]), "=r"(r[3]) : "r"(a));
}
__device__ __forceinline__ void cpa16(uint32_t dst, const void* src, int srcsz) {
    asm volatile("cp.async.cg.shared.global [%0], [%1], 16, %2;"
        :: "r"(dst), "l"(src), "r"(srcsz) : "memory");
}
#define CP_COMMIT() asm volatile("cp.async.commit_group;" ::: "memory")
#define CP_WAIT(n)  asm volatile("cp.async.wait_group %0;" :: "n"(n) : "memory")

// smem tile byte offset: 128B rows (64 fp16), seg = 16B segment (0..7), XOR swizzle
__device__ __forceinline__ uint32_t sw_off(int row, int seg) {
    return (uint32_t)(row * 128 + ((seg ^ (row & 7)) << 4));
}

// ---------------- 1) gating: logits, top-2, softmax; emits x fp16 ----------
__global__ void gate_kernel(const float* __restrict__ x,
                            const float* __restrict__ Wg) {
    __shared__ float xs[128][68];
    __shared__ float wgs[64][8];
    const int tid = threadIdx.x;
    const int t0  = blockIdx.x * 128;
    float acc[E_NUM];
#pragma unroll
    for (int e = 0; e < E_NUM; e++) acc[e] = 0.f;

    for (int k0 = 0; k0 < D_DIM; k0 += 64) {
#pragma unroll
        for (int i = 0; i < 4; i++) {
            int idx = tid + i * 128;
            wgs[idx >> 3][idx & 7] = Wg[(k0 + (idx >> 3)) * E_NUM + (idx & 7)];
        }
#pragma unroll
        for (int i = 0; i < 16; i++) {
            int f4  = i * 128 + tid;
            int row = f4 >> 4;
            int c4  = f4 & 15;
            float4 v = *(const float4*)(x + (size_t)(t0 + row) * D_DIM + k0 + c4 * 4);
            *(float4*)&xs[row][c4 * 4] = v;
            size_t o = (size_t)(t0 + row) * D_DIM + k0 + c4 * 4;
            *(uint2*)(g_Xf + o) = make_uint2(packh2(v.x, v.y), packh2(v.z, v.w));
        }
        __syncthreads();
#pragma unroll 8
        for (int k = 0; k < 64; k++) {
            float xv = xs[tid][k];
#pragma unroll
            for (int e = 0; e < E_NUM; e++) acc[e] = fmaf(xv, wgs[k][e], acc[e]);
        }
        __syncthreads();
    }
    int e0 = 0; float v0 = acc[0];
#pragma unroll
    for (int e = 1; e < E_NUM; e++) if (acc[e] > v0) { v0 = acc[e]; e0 = e; }
    int e1 = -1; float v1 = -INFINITY;
#pragma unroll
    for (int e = 0; e < E_NUM; e++) if (e != e0 && acc[e] > v1) { v1 = acc[e]; e1 = e; }
    float p1 = __expf(v1 - v0);
    float inv = 1.f / (1.f + p1);
    int t = t0 + tid;
    g_e0[t] = e0; g_e1[t] = e1;
    g_g0[t] = inv; g_g1[t] = p1 * inv;
}

// ---------------- 2) setup: reductions, offsets, losses ----------------
__global__ void setup_kernel(float* __restrict__ out) {
    __shared__ float simp[E_NUM][256];
    __shared__ int   scnt[E_NUM][256];
    const int tid = threadIdx.x;
    float imp[E_NUM]; int cnt[E_NUM];
#pragma unroll
    for (int e = 0; e < E_NUM; e++) { imp[e] = 0.f; cnt[e] = 0; }
    for (int t = tid; t < T_TOK; t += 256) {
        int a = g_e0[t]; imp[a] += g_g0[t]; cnt[a]++;
        int b = g_e1[t]; imp[b] += g_g1[t]; cnt[b]++;
    }
#pragma unroll
    for (int e = 0; e < E_NUM; e++) { simp[e][tid] = imp[e]; scnt[e][tid] = cnt[e]; }
    __syncthreads();
    for (int s = 128; s > 0; s >>= 1) {
        if (tid < s) {
#pragma unroll
            for (int e = 0; e < E_NUM; e++) {
                simp[e][tid] += simp[e][tid + s];
                scnt[e][tid] += scnt[e][tid + s];
            }
        }
        __syncthreads();
    }
    if (tid == 0) {
        const float eps = 1e-10f;
        int off = 0;
        float mi = 0.f, ml = 0.f;
#pragma unroll
        for (int e = 0; e < E_NUM; e++) {
            g_off[e] = off; g_cnt[e] = scnt[e][0]; g_cursor[e] = 0;
            off += scnt[e][0];
            mi += simp[e][0];
            ml += (float)scnt[e][0];
        }
        mi /= E_NUM; ml /= E_NUM;
        float vi = 0.f, vl = 0.f;
#pragma unroll
        for (int e = 0; e < E_NUM; e++) {
            float di = simp[e][0] - mi; vi += di * di;
            float dl = (float)scnt[e][0] - ml; vl += dl * dl;
        }
        vi /= (E_NUM - 1); vl /= (E_NUM - 1);
        out[(size_t)T_TOK * D_DIM]     = vi / (mi * mi + eps);
        out[(size_t)T_TOK * D_DIM + 1] = vl / (ml * ml + eps);
    }
}

// ---------------- 3) scatter ----------------
__global__ void scatter_kernel() {
    int t = blockIdx.x * 256 + threadIdx.x;
    if (t >= T_TOK) return;
    {
        int e = g_e0[t];
        int p = atomicAdd(&g_cursor[e], 1);
        int s = g_off[e] + p;
        g_tok[s] = t; g_gate[s] = g_g0[t];
    }
    {
        int e = g_e1[t];
        int p = atomicAdd(&g_cursor[e], 1);
        int s = g_off[e] + p;
        g_tok[s] = t; g_gate[s] = g_g1[t];
    }
}

// ------------- weight transpose + fp16 convert -------------
template <int R, int C>
__device__ __forceinline__ void transpose_half(const float* __restrict__ s,
                                               uint16_t* __restrict__ d) {
    __shared__ float tile[32][33];
    int c0 = blockIdx.x * 32, r0 = blockIdx.y * 32;
#pragma unroll
    for (int i = 0; i < 32; i += 8)
        tile[threadIdx.y + i][threadIdx.x] = s[(size_t)(r0 + threadIdx.y + i) * C + c0 + threadIdx.x];
    __syncthreads();
#pragma unroll
    for (int i = 0; i < 32; i += 8) {
        float v = tile[threadIdx.x][threadIdx.y + i];
        __half h = __float2half_rn(v);
        d[(size_t)(c0 + threadIdx.y + i) * R + r0 + threadIdx.x] = *(uint16_t*)&h;
    }
}
__global__ void conv_w1_kernel(const float* __restrict__ W1) {
    int e = blockIdx.z;
    size_t eo = (size_t)e * D_DIM * H_DIM;
    transpose_half<D_DIM, H_DIM>(W1 + eo, g_W1f + eo);
}
__global__ void conv_w2_kernel(const float* __restrict__ W2) {
    int e = blockIdx.z;
    size_t eo = (size_t)e * H_DIM * D_DIM;
    transpose_half<H_DIM, D_DIM>(W2 + eo, g_W2f + eo);
}

// ---------------- shared GEMM smem ----------------
struct GS {
    uint16_t A[2][TILE_U16];
    uint16_t B[2][TILE_U16];
    int   toks[BM];
    float gates[BM];
    float bias[BN];
};
#define GS_BYTES sizeof(GS)

// compute one k64 chunk from stage st
__device__ __forceinline__ void compute_chunk(GS* gs, int st, int wm, int wn, int lid,
                                              float acc[4][4][4]) {
    const int r_ = lid & 7, mat = lid >> 3;
    uint32_t pA = smem_u32(gs->A[st]);
    uint32_t pB = smem_u32(gs->B[st]);
#pragma unroll
    for (int s = 0; s < 4; s++) {               // 4 k16 steps
        uint32_t bf[4][2];
#pragma unroll
        for (int np = 0; np < 2; np++) {
            int row = wn * 32 + np * 16 + ((mat >> 1) << 3) + r_;
            int seg = (s << 1) | (mat & 1);
            uint32_t t[4];
            ldsm4(t, pB + sw_off(row, seg));
            bf[np * 2][0]     = t[0]; bf[np * 2][1]     = t[1];
            bf[np * 2 + 1][0] = t[2]; bf[np * 2 + 1][1] = t[3];
        }
#pragma unroll
        for (int mi = 0; mi < 4; mi++) {
            int row = wm * 64 + mi * 16 + ((mat & 1) << 3) + r_;
            int seg = (s << 1) | (mat >> 1);
            uint32_t af[4];
            ldsm4(af, pA + sw_off(row, seg));
#pragma unroll
            for (int ni = 0; ni < 4; ni++)
                mma16816(acc[mi][ni], af, bf[ni]);
        }
    }
}

// fill one stage: A gathered by tok list, B linear
__device__ __forceinline__ void fill_stage(GS* gs, int st, int tid,
                                           const uint16_t* __restrict__ A,
                                           const uint16_t* __restrict__ B,
                                           int k0, int lda, int ldb, bool gatherA, int mrem) {
    uint32_t pA = smem_u32(gs->A[st]);
    uint32_t pB = smem_u32(gs->B[st]);
#pragma unroll
    for (int i = 0; i < 4; i++) {
        int id  = tid + i * 256;   // 0..1023
        int row = id >> 3, seg = id & 7;
        uint32_t d = sw_off(row, seg);
        int vs; size_t grow;
        if (gatherA) {
            int tok = gs->toks[row];
            vs = (tok >= 0) ? 16 : 0;
            grow = (tok >= 0) ? (size_t)tok : 0;
        } else {
            vs = (row < mrem) ? 16 : 0;
            grow = (row < mrem) ? (size_t)row : 0;
        }
        cpa16(pA + d, A + grow * lda + k0 + seg * 8, vs);
        cpa16(pB + d, B + (size_t)row * ldb + k0 + seg * 8, 16);
    }
}

// ---------------- 4) GEMM1: H = relu(gather(x) @ W1 + b1) ----------------
__global__ __launch_bounds__(256, 2)
void gemm1_mma(const float* __restrict__ b1) {
    extern __shared__ __align__(16) char smraw[];
    GS* gs = (GS*)smraw;
    const int e   = blockIdx.z;
    const int cnt = g_cnt[e];
    const int m0  = blockIdx.x * BM;
    if (m0 >= cnt) return;
    const int n0   = blockIdx.y * BN;
    const int off  = g_off[e];
    const int mrem = cnt - m0;
    const int tid  = threadIdx.x;
    const int wid  = tid >> 5, lid = tid & 31;
    const int wm = wid >> 2, wn = wid & 3;
    const int g = lid >> 2, q = lid & 3;

    if (tid < BM) {
        gs->toks[tid] = (tid < mrem) ? g_tok[off + m0 + tid] : -1;
        gs->bias[tid] = b1[(size_t)e * H_DIM + n0 + tid];
    }
    __syncthreads();

    float acc[4][4][4];
#pragma unroll
    for (int a = 0; a < 4; a++)
#pragma unroll
        for (int b = 0; b < 4; b++)
#pragma unroll
            for (int c = 0; c < 4; c++) acc[a][b][c] = 0.f;

    const uint16_t* Bp = g_W1f + ((size_t)e * H_DIM + n0) * D_DIM;

    const int NC = D_DIM / BK;   // 8
    fill_stage(gs, 0, tid, g_Xf, Bp, 0, D_DIM, D_DIM, true, mrem);
    CP_COMMIT();
    for (int c = 0; c < NC; c++) {
        int st = c & 1;
        if (c + 1 < NC) {
            fill_stage(gs, st ^ 1, tid, g_Xf, Bp, (c + 1) * BK, D_DIM, D_DIM, true, mrem);
            CP_COMMIT();
            CP_WAIT(1);
        } else {
            CP_WAIT(0);
        }
        __syncthreads();
        compute_chunk(gs, st, wm, wn, lid, acc);
        __syncthreads();
    }

    // epilogue: bias + relu -> fp16 H
#pragma unroll
    for (int mi = 0; mi < 4; mi++) {
#pragma unroll
        for (int h = 0; h < 2; h++) {
            int mrow = wm * 64 + mi * 16 + g + h * 8;
            if (mrow < mrem) {
                size_t rb = (size_t)(off + m0 + mrow) * H_DIM + n0;
#pragma unroll
                for (int ni = 0; ni < 4; ni++) {
                    int n = wn * 32 + ni * 8 + q * 2;
                    float v0 = fmaxf(acc[mi][ni][h * 2 + 0] + gs->bias[n], 0.f);
                    float v1 = fmaxf(acc[mi][ni][h * 2 + 1] + gs->bias[n + 1], 0.f);
                    *(uint32_t*)(g_Hf + rb + n) = packh2(v0, v1);
                }
            }
        }
    }
}

// ---------------- 5) GEMM2: out += gate * (H @ W2 + b2) ----------------
__global__ __launch_bounds__(256, 2)
void gemm2_mma(const float* __restrict__ b2, float* __restrict__ out) {
    extern __shared__ __align__(16) char smraw[];
    GS* gs = (GS*)smraw;
    const int e   = blockIdx.z;
    const int cnt = g_cnt[e];
    const int m0  = blockIdx.x * BM;
    if (m0 >= cnt) return;
    const int n0   = blockIdx.y * BN;
    const int off  = g_off[e];
    const int mrem = cnt - m0;
    const int tid  = threadIdx.x;
    const int wid  = tid >> 5, lid = tid & 31;
    const int wm = wid >> 2, wn = wid & 3;
    const int g = lid >> 2, q = lid & 3;

    if (tid < BM) {
        int valid = tid < mrem;
        int s = off + m0 + tid;
        gs->toks[tid]  = valid ? g_tok[s] : -1;
        gs->gates[tid] = valid ? g_gate[s] : 0.f;
        gs->bias[tid]  = b2[(size_t)e * D_DIM + n0 + tid];
    }
    __syncthreads();

    float acc[4][4][4];
#pragma unroll
    for (int a = 0; a < 4; a++)
#pragma unroll
        for (int b = 0; b < 4; b++)
#pragma unroll
            for (int c = 0; c < 4; c++) acc[a][b][c] = 0.f;

    const uint16_t* Ap = g_Hf + (size_t)(off + m0) * H_DIM;
    const uint16_t* Bp = g_W2f + ((size_t)e * D_DIM + n0) * H_DIM;

    const int NC = H_DIM / BK;   // 16
    fill_stage(gs, 0, tid, Ap, Bp, 0, H_DIM, H_DIM, false, mrem);
    CP_COMMIT();
    for (int c = 0; c < NC; c++) {
        int st = c & 1;
        if (c + 1 < NC) {
            fill_stage(gs, st ^ 1, tid, Ap, Bp, (c + 1) * BK, H_DIM, H_DIM, false, mrem);
            CP_COMMIT();
            CP_WAIT(1);
        } else {
            CP_WAIT(0);
        }
        __syncthreads();
        compute_chunk(gs, st, wm, wn, lid, acc);
        __syncthreads();
    }

    // epilogue: (acc + bias) * gate -> atomicAdd combine
#pragma unroll
    for (int mi = 0; mi < 4; mi++) {
#pragma unroll
        for (int h = 0; h < 2; h++) {
            int mrow = wm * 64 + mi * 16 + g + h * 8;
            if (mrow < mrem) {
                int tok  = gs->toks[mrow];
                float gt = gs->gates[mrow];
                float* dst = out + (size_t)tok * D_DIM + n0;
#pragma unroll
                for (int ni = 0; ni < 4; ni++) {
                    int n = wn * 32 + ni * 8 + q * 2;
                    atomicAdd(&dst[n],     (acc[mi][ni][h * 2 + 0] + gs->bias[n]) * gt);
                    atomicAdd(&dst[n + 1], (acc[mi][ni][h * 2 + 1] + gs->bias[n + 1]) * gt);
                }
            }
        }
    }
}

// ---------------- launch ----------------
extern "C" void kernel_launch(void* const* d_in, const int* in_sizes, int n_in,
                              void* d_out, int out_size) {
    const float* x  = (const float*)d_in[0];
    const float* Wg = (const float*)d_in[1];
    const float* W1 = (const float*)d_in[2];
    const float* b1 = (const float*)d_in[3];
    const float* W2 = (const float*)d_in[4];
    const float* b2 = (const float*)d_in[5];
    float* out = (float*)d_out;

    static bool attr_done = false;
    if (!attr_done) {
        cudaFuncSetAttribute(gemm1_mma, cudaFuncAttributeMaxDynamicSharedMemorySize, (int)GS_BYTES);
        cudaFuncSetAttribute(gemm2_mma, cudaFuncAttributeMaxDynamicSharedMemorySize, (int)GS_BYTES);
        attr_done = true;
    }

    cudaMemsetAsync(out, 0, (size_t)T_TOK * D_DIM * sizeof(float));

    gate_kernel<<<T_TOK / 128, 128>>>(x, Wg);
    setup_kernel<<<1, 256>>>(out);
    scatter_kernel<<<(T_TOK + 255) / 256, 256>>>();

    conv_w1_kernel<<<dim3(H_DIM / 32, D_DIM / 32, E_NUM), dim3(32, 8)>>>(W1);
    conv_w2_kernel<<<dim3(D_DIM / 32, H_DIM / 32, E_NUM), dim3(32, 8)>>>(W2);

    dim3 g1(T_TOK / BM, H_DIM / BN, E_NUM);   // (64, 8, 8), empty tiles exit
    gemm1_mma<<<g1, 256, GS_BYTES>>>(b1);

    dim3 g2(T_TOK / BM, D_DIM / BN, E_NUM);   // (64, 4, 8)
    gemm2_mma<<<g2, 256, GS_BYTES>>>(b2, out);
}